// round 4
// baseline (speedup 1.0000x reference)
#include <cuda_runtime.h>
#include <cuda_bf16.h>
#include <cstdint>

// Problem constants (fixed by the dataset).
#define BSZ     16
#define DIM     4096
#define NH      32
#define NKV     8
#define HD      128
#define MSL     4096
#define NSPLIT  8
#define SCHUNK  512          // MSL / NSPLIT
#define KVROW   (NKV * HD)   // 1024 floats per cache position
#define SCALE   0.08838834764831845f   // 1/sqrt(128)

// ---------------------------------------------------------------------------
// Scratch (no allocations allowed -> __device__ globals)
// ---------------------------------------------------------------------------
__device__ float g_q[BSZ * NH * HD];                 // rope'd q  [b][h][d]
__device__ float g_k[BSZ * NKV * HD];                // rope'd new k [b][hk][d]
__device__ float g_v[BSZ * NKV * HD];                // new v        [b][hk][d]
__device__ float g_op[BSZ * NKV * NSPLIT * 4 * HD];  // per-split partial O
__device__ float g_m[BSZ * NKV * NSPLIT * 4];        // per-split max
__device__ float g_l[BSZ * NKV * NSPLIT * 4];        // per-split sum
__device__ float g_attn[BSZ * DIM];                  // combined attention out

// start_pos may arrive as int32/int64/float32 -> defensive decode
__device__ __forceinline__ int load_sp(const int* p) {
    int v = *p;
    if (v < 0 || v >= 1000000) v = (int)__int_as_float(v);
    return v;
}

// ---------------------------------------------------------------------------
// Kernel 1: QKV GEMV.  out[b][row] = dot(x[b], W[row]).
// One warp handles 4 consecutive rows x 16 batches (R=4 row blocking to
// amortize x reads through L1).  6144 rows total -> 1536 warps -> 192 blocks.
// ---------------------------------------------------------------------------
__global__ void __launch_bounds__(256) k_gemv_qkv(
    const float* __restrict__ x,
    const float* __restrict__ wq,
    const float* __restrict__ wk,
    const float* __restrict__ wv)
{
    const int gw   = (blockIdx.x * blockDim.x + threadIdx.x) >> 5;
    const int lane = threadIdx.x & 31;
    const int r0   = gw * 4;             // first row of this warp's group

    const float* W; float* dst; int stride; int rbase;
    if (r0 < 4096)      { W = wq; dst = g_q; stride = DIM;   rbase = r0;        }
    else if (r0 < 5120) { W = wk; dst = g_k; stride = KVROW; rbase = r0 - 4096; }
    else                { W = wv; dst = g_v; stride = KVROW; rbase = r0 - 5120; }

    const float* w0p = W + (size_t)(rbase + 0) * DIM;
    const float* w1p = W + (size_t)(rbase + 1) * DIM;
    const float* w2p = W + (size_t)(rbase + 2) * DIM;
    const float* w3p = W + (size_t)(rbase + 3) * DIM;

    float acc[4][16];
#pragma unroll
    for (int r = 0; r < 4; r++)
#pragma unroll
        for (int b = 0; b < 16; b++) acc[r][b] = 0.f;

    const int off = lane * 4;
    for (int c = 0; c < DIM; c += 128) {
        const float4 w0 = *reinterpret_cast<const float4*>(w0p + c + off);
        const float4 w1 = *reinterpret_cast<const float4*>(w1p + c + off);
        const float4 w2 = *reinterpret_cast<const float4*>(w2p + c + off);
        const float4 w3 = *reinterpret_cast<const float4*>(w3p + c + off);
#pragma unroll
        for (int b = 0; b < 16; b++) {
            const float4 xv = *reinterpret_cast<const float4*>(x + b * DIM + c + off);
            acc[0][b] += w0.x*xv.x + w0.y*xv.y + w0.z*xv.z + w0.w*xv.w;
            acc[1][b] += w1.x*xv.x + w1.y*xv.y + w1.z*xv.z + w1.w*xv.w;
            acc[2][b] += w2.x*xv.x + w2.y*xv.y + w2.z*xv.z + w2.w*xv.w;
            acc[3][b] += w3.x*xv.x + w3.y*xv.y + w3.z*xv.z + w3.w*xv.w;
        }
    }

#pragma unroll
    for (int r = 0; r < 4; r++) {
        float res = 0.f;
#pragma unroll
        for (int b = 0; b < 16; b++) {
            float v = acc[r][b];
            v += __shfl_xor_sync(0xffffffffu, v, 16);
            v += __shfl_xor_sync(0xffffffffu, v, 8);
            v += __shfl_xor_sync(0xffffffffu, v, 4);
            v += __shfl_xor_sync(0xffffffffu, v, 2);
            v += __shfl_xor_sync(0xffffffffu, v, 1);
            if (lane == b) res = v;
        }
        if (lane < 16) dst[(size_t)lane * stride + rbase + r] = res;
    }
}

// ---------------------------------------------------------------------------
// Kernel 2: RoPE on q (16*32 heads) and new k (16*8 heads).
// Interleaved pairs: (t[2i], t[2i+1]) rotated by (cos[i], sin[i]).
// 40960 pairs -> 160 blocks x 256 threads.
// ---------------------------------------------------------------------------
__global__ void k_rope(const float* __restrict__ fc, const float* __restrict__ fs)
{
    const int t = blockIdx.x * blockDim.x + threadIdx.x;
    float* base; int idx;
    if (t < BSZ * NH * 64) { base = g_q; idx = t; }
    else {
        idx = t - BSZ * NH * 64;
        if (idx >= BSZ * NKV * 64) return;
        base = g_k;
    }
    const int i = idx & 63;
    const float c = fc[i], s = fs[i];
    const float a  = base[2 * idx];
    const float bb = base[2 * idx + 1];
    base[2 * idx]     = a * c - bb * s;
    base[2 * idx + 1] = a * s + bb * c;
}

// ---------------------------------------------------------------------------
// Kernel 3: split-KV attention partials.
// grid = (NSPLIT, NKV, BSZ), 256 threads.
// Each block: 512-position chunk for one (b, kv-head), all 4 Q heads of the
// GQA group, two-pass chunk softmax, writes (m, l, o_partial).
// ---------------------------------------------------------------------------
__global__ void __launch_bounds__(256) k_attn(
    const float* __restrict__ cache_k,
    const float* __restrict__ cache_v,
    const int*   __restrict__ sp_ptr)
{
    const int split = blockIdx.x;
    const int hk    = blockIdx.y;
    const int b     = blockIdx.z;
    const int sp    = load_sp(sp_ptr);
    const int pos0  = split * SCHUNK;
    const int tid   = threadIdx.x;
    const int lane  = tid & 31;
    const int warp  = tid >> 5;

    __shared__ float sc[4][SCHUNK];      // scores then exp'd probs
    __shared__ float redm[4][8];
    __shared__ float redl[4][8];
    __shared__ float fm[4];

    // Per-lane q fragments: 4 heads x float4 at dims [lane*4, lane*4+3]
    float4 ql[4];
#pragma unroll
    for (int j = 0; j < 4; j++)
        ql[j] = *reinterpret_cast<const float4*>(
            g_q + (size_t)b * DIM + (hk * 4 + j) * HD + lane * 4);

    // ---- Phase A: scores (stream K chunk once) ----
    const size_t kb = (size_t)b * MSL * KVROW + (size_t)hk * HD;
    for (int p = warp; p < SCHUNK; p += 8) {
        const int pos = pos0 + p;
        float4 k4;
        if (pos < sp)
            k4 = *reinterpret_cast<const float4*>(
                cache_k + kb + (size_t)pos * KVROW + lane * 4);
        else if (pos == sp)
            k4 = *reinterpret_cast<const float4*>(
                g_k + (b * NKV + hk) * HD + lane * 4);
        else
            k4 = make_float4(0.f, 0.f, 0.f, 0.f);

        float d0 = k4.x*ql[0].x + k4.y*ql[0].y + k4.z*ql[0].z + k4.w*ql[0].w;
        float d1 = k4.x*ql[1].x + k4.y*ql[1].y + k4.z*ql[1].z + k4.w*ql[1].w;
        float d2 = k4.x*ql[2].x + k4.y*ql[2].y + k4.z*ql[2].z + k4.w*ql[2].w;
        float d3 = k4.x*ql[3].x + k4.y*ql[3].y + k4.z*ql[3].z + k4.w*ql[3].w;

        // joint 4-value warp reduce in 9 shuffles; lane l ends with sum(d_{l&3})
        d0 += __shfl_xor_sync(0xffffffffu, d0, 1);
        d1 += __shfl_xor_sync(0xffffffffu, d1, 1);
        d2 += __shfl_xor_sync(0xffffffffu, d2, 1);
        d3 += __shfl_xor_sync(0xffffffffu, d3, 1);
        float aa = (lane & 1) ? d1 : d0;
        float bb = (lane & 1) ? d3 : d2;
        aa += __shfl_xor_sync(0xffffffffu, aa, 2);
        bb += __shfl_xor_sync(0xffffffffu, bb, 2);
        float cc = (lane & 2) ? bb : aa;
        cc += __shfl_xor_sync(0xffffffffu, cc, 4);
        cc += __shfl_xor_sync(0xffffffffu, cc, 8);
        cc += __shfl_xor_sync(0xffffffffu, cc, 16);
        if (lane < 4) sc[lane][p] = (pos <= sp) ? cc * SCALE : -1e30f;
    }
    __syncthreads();

    // ---- Phase B: chunk max ----
    float lm[4] = {-1e30f, -1e30f, -1e30f, -1e30f};
    for (int p = tid; p < SCHUNK; p += 256) {
#pragma unroll
        for (int h = 0; h < 4; h++) lm[h] = fmaxf(lm[h], sc[h][p]);
    }
#pragma unroll
    for (int h = 0; h < 4; h++) {
        float v = lm[h];
        v = fmaxf(v, __shfl_xor_sync(0xffffffffu, v, 16));
        v = fmaxf(v, __shfl_xor_sync(0xffffffffu, v, 8));
        v = fmaxf(v, __shfl_xor_sync(0xffffffffu, v, 4));
        v = fmaxf(v, __shfl_xor_sync(0xffffffffu, v, 2));
        v = fmaxf(v, __shfl_xor_sync(0xffffffffu, v, 1));
        if (lane == 0) redm[h][warp] = v;
    }
    __syncthreads();
    if (tid < 4) {
        float m = redm[tid][0];
#pragma unroll
        for (int w = 1; w < 8; w++) m = fmaxf(m, redm[tid][w]);
        fm[tid] = m;
    }
    __syncthreads();

    // ---- exp + row-sum ----
    float ll[4] = {0.f, 0.f, 0.f, 0.f};
    for (int p = tid; p < SCHUNK; p += 256) {
#pragma unroll
        for (int h = 0; h < 4; h++) {
            const float e = __expf(sc[h][p] - fm[h]);
            sc[h][p] = e;
            ll[h] += e;
        }
    }
#pragma unroll
    for (int h = 0; h < 4; h++) {
        float v = ll[h];
        v += __shfl_xor_sync(0xffffffffu, v, 16);
        v += __shfl_xor_sync(0xffffffffu, v, 8);
        v += __shfl_xor_sync(0xffffffffu, v, 4);
        v += __shfl_xor_sync(0xffffffffu, v, 2);
        v += __shfl_xor_sync(0xffffffffu, v, 1);
        if (lane == 0) redl[h][warp] = v;
    }
    __syncthreads();

    const size_t pi = (size_t)(b * NKV + hk) * NSPLIT + split;
    if (tid < 4) {
        float s = 0.f;
#pragma unroll
        for (int w = 0; w < 8; w++) s += redl[tid][w];
        g_m[pi * 4 + tid] = fm[tid];
        g_l[pi * 4 + tid] = s;
    }
    __syncthreads();   // sc[] fully updated before phase C reads it

    // ---- Phase C: stream V chunk once, accumulate O for 4 heads ----
    const int h2 = tid >> 7;        // 0/1 : handles heads h2 and h2+2
    const int d  = tid & 127;
    float acc0 = 0.f, acc1 = 0.f;
    const float* vbase = cache_v + (size_t)b * MSL * KVROW + (size_t)hk * HD + d;
    const float  gvv   = g_v[(b * NKV + hk) * HD + d];
#pragma unroll 8
    for (int p = 0; p < SCHUNK; p++) {
        const int pos = pos0 + p;
        const float cv = vbase[(size_t)pos * KVROW];     // pos < MSL always
        const float v  = (pos == sp) ? gvv : cv;
        acc0 = fmaf(sc[h2][p],     v, acc0);
        acc1 = fmaf(sc[h2 + 2][p], v, acc1);
    }
    float* op = g_op + pi * 4 * HD;
    op[h2 * HD + d]       = acc0;
    op[(h2 + 2) * HD + d] = acc1;
}

// ---------------------------------------------------------------------------
// Kernel 4: combine split partials into g_attn.  512 blocks x 128 threads.
// ---------------------------------------------------------------------------
__global__ void k_combine()
{
    const int bh = blockIdx.x;          // b*32 + h
    const int d  = threadIdx.x;
    const int b  = bh >> 5, h = bh & 31;
    const int hk = h >> 2, j = h & 3;
    const int base = (b * NKV + hk) * NSPLIT;

    float M = -1e30f;
#pragma unroll
    for (int s = 0; s < NSPLIT; s++) M = fmaxf(M, g_m[(base + s) * 4 + j]);
    float den = 0.f, o = 0.f;
#pragma unroll
    for (int s = 0; s < NSPLIT; s++) {
        const float w = __expf(g_m[(base + s) * 4 + j] - M);
        den += g_l[(base + s) * 4 + j] * w;
        o   += g_op[((size_t)(base + s) * 4 + j) * HD + d] * w;
    }
    g_attn[b * DIM + h * HD + d] = o / den;
}

// ---------------------------------------------------------------------------
// Kernel 5: output GEMV over wo.  4096 rows -> 1024 warps -> 128 blocks.
// out[b][e] = dot(g_attn[b], wo[e]).
// ---------------------------------------------------------------------------
__global__ void __launch_bounds__(256) k_gemv_out(
    const float* __restrict__ wo, float* __restrict__ out)
{
    const int gw   = (blockIdx.x * blockDim.x + threadIdx.x) >> 5;
    const int lane = threadIdx.x & 31;
    const int r0   = gw * 4;

    const float* w0p = wo + (size_t)(r0 + 0) * DIM;
    const float* w1p = wo + (size_t)(r0 + 1) * DIM;
    const float* w2p = wo + (size_t)(r0 + 2) * DIM;
    const float* w3p = wo + (size_t)(r0 + 3) * DIM;

    float acc[4][16];
#pragma unroll
    for (int r = 0; r < 4; r++)
#pragma unroll
        for (int b = 0; b < 16; b++) acc[r][b] = 0.f;

    const int off = lane * 4;
    for (int c = 0; c < DIM; c += 128) {
        const float4 w0 = *reinterpret_cast<const float4*>(w0p + c + off);
        const float4 w1 = *reinterpret_cast<const float4*>(w1p + c + off);
        const float4 w2 = *reinterpret_cast<const float4*>(w2p + c + off);
        const float4 w3 = *reinterpret_cast<const float4*>(w3p + c + off);
#pragma unroll
        for (int b = 0; b < 16; b++) {
            const float4 xv = *reinterpret_cast<const float4*>(g_attn + b * DIM + c + off);
            acc[0][b] += w0.x*xv.x + w0.y*xv.y + w0.z*xv.z + w0.w*xv.w;
            acc[1][b] += w1.x*xv.x + w1.y*xv.y + w1.z*xv.z + w1.w*xv.w;
            acc[2][b] += w2.x*xv.x + w2.y*xv.y + w2.z*xv.z + w2.w*xv.w;
            acc[3][b] += w3.x*xv.x + w3.y*xv.y + w3.z*xv.z + w3.w*xv.w;
        }
    }

#pragma unroll
    for (int r = 0; r < 4; r++) {
        float res = 0.f;
#pragma unroll
        for (int b = 0; b < 16; b++) {
            float v = acc[r][b];
            v += __shfl_xor_sync(0xffffffffu, v, 16);
            v += __shfl_xor_sync(0xffffffffu, v, 8);
            v += __shfl_xor_sync(0xffffffffu, v, 4);
            v += __shfl_xor_sync(0xffffffffu, v, 2);
            v += __shfl_xor_sync(0xffffffffu, v, 1);
            if (lane == b) res = v;
        }
        if (lane < 16) out[(size_t)lane * DIM + r0 + r] = res;
    }
}

// ---------------------------------------------------------------------------
// Launch: inputs are (x, wq, wk, wv, wo, cache_k, cache_v, fcos, fsin, start_pos)
// ---------------------------------------------------------------------------
extern "C" void kernel_launch(void* const* d_in, const int* in_sizes, int n_in,
                              void* d_out, int out_size)
{
    const float* x  = (const float*)d_in[0];
    const float* wq = (const float*)d_in[1];
    const float* wk = (const float*)d_in[2];
    const float* wv = (const float*)d_in[3];
    const float* wo = (const float*)d_in[4];
    const float* ck = (const float*)d_in[5];
    const float* cv = (const float*)d_in[6];
    const float* fc = (const float*)d_in[7];
    const float* fs = (const float*)d_in[8];
    const int*   sp = (const int*)d_in[9];
    float* out = (float*)d_out;

    k_gemv_qkv<<<192, 256>>>(x, wq, wk, wv);
    k_rope<<<160, 256>>>(fc, fs);
    dim3 ag(NSPLIT, NKV, BSZ);
    k_attn<<<ag, 256>>>(ck, cv, sp);
    k_combine<<<BSZ * NH, HD>>>();
    k_gemv_out<<<128, 256>>>(wo, out);
}

// round 6
// speedup vs baseline: 1.0871x; 1.0871x over previous
#include <cuda_runtime.h>
#include <cuda_bf16.h>
#include <cstdint>

// Problem constants (fixed by the dataset).
#define BSZ     16
#define DIM     4096
#define NH      32
#define NKV     8
#define HD      128
#define MSL     4096
#define NSPLIT  16
#define SCHUNK  256          // MSL / NSPLIT
#define KVROW   (NKV * HD)   // 1024 floats per cache position
#define SCALE   0.08838834764831845f   // 1/sqrt(128)

// ---------------------------------------------------------------------------
// Scratch (no allocations allowed -> __device__ globals, 16B aligned for
// vectorized access)
// ---------------------------------------------------------------------------
__device__ __align__(16) float g_q[BSZ * NH * HD];
__device__ __align__(16) float g_k[BSZ * NKV * HD];
__device__ __align__(16) float g_v[BSZ * NKV * HD];
__device__ __align__(16) float g_op[BSZ * NKV * NSPLIT * 4 * HD];   // 4 MB
__device__ float g_m[BSZ * NKV * NSPLIT * 4];
__device__ float g_l[BSZ * NKV * NSPLIT * 4];
__device__ __align__(16) float g_attn[BSZ * DIM];

// start_pos may arrive as int32/int64/float32 -> defensive decode
__device__ __forceinline__ int load_sp(const int* p) {
    int v = *p;
    if (v < 0 || v >= 1000000) v = (int)__int_as_float(v);
    return v;
}

// Packed fp32x2 FMA (sm_100a+): lane-wise d = a*b + c on two packed floats.
__device__ __forceinline__ unsigned long long ffma2(
    unsigned long long a, unsigned long long b, unsigned long long c)
{
    unsigned long long d;
    asm("fma.rn.f32x2 %0, %1, %2, %3;" : "=l"(d) : "l"(a), "l"(b), "l"(c));
    return d;
}
__device__ __forceinline__ float ull_lo(unsigned long long v) {
    return __uint_as_float((unsigned)(v & 0xffffffffull));
}
__device__ __forceinline__ float ull_hi(unsigned long long v) {
    return __uint_as_float((unsigned)(v >> 32));
}

// ---------------------------------------------------------------------------
// Kernel 1: QKV GEMV with packed f32x2 accumulation.
// One warp: 4 rows x 16 batches.  6144 rows -> 1536 warps -> 192 blocks.
// ---------------------------------------------------------------------------
__global__ void __launch_bounds__(256) k_gemv_qkv(
    const float* __restrict__ x,
    const float* __restrict__ wq,
    const float* __restrict__ wk,
    const float* __restrict__ wv)
{
    const int gw   = (blockIdx.x * blockDim.x + threadIdx.x) >> 5;
    const int lane = threadIdx.x & 31;
    const int r0   = gw * 4;

    const float* W; float* dst; int stride; int rbase;
    if (r0 < 4096)      { W = wq; dst = g_q; stride = DIM;   rbase = r0;        }
    else if (r0 < 5120) { W = wk; dst = g_k; stride = KVROW; rbase = r0 - 4096; }
    else                { W = wv; dst = g_v; stride = KVROW; rbase = r0 - 5120; }

    const float* w0p = W + (size_t)(rbase + 0) * DIM;
    const float* w1p = W + (size_t)(rbase + 1) * DIM;
    const float* w2p = W + (size_t)(rbase + 2) * DIM;
    const float* w3p = W + (size_t)(rbase + 3) * DIM;

    unsigned long long acc[4][16];
#pragma unroll
    for (int r = 0; r < 4; r++)
#pragma unroll
        for (int b = 0; b < 16; b++) acc[r][b] = 0ull;

    const int off = lane * 4;
    for (int c = 0; c < DIM; c += 128) {
        const ulonglong2 w0 = *reinterpret_cast<const ulonglong2*>(w0p + c + off);
        const ulonglong2 w1 = *reinterpret_cast<const ulonglong2*>(w1p + c + off);
        const ulonglong2 w2 = *reinterpret_cast<const ulonglong2*>(w2p + c + off);
        const ulonglong2 w3 = *reinterpret_cast<const ulonglong2*>(w3p + c + off);
#pragma unroll
        for (int b = 0; b < 16; b++) {
            const ulonglong2 xv =
                *reinterpret_cast<const ulonglong2*>(x + (size_t)b * DIM + c + off);
            acc[0][b] = ffma2(w0.x, xv.x, acc[0][b]);
            acc[0][b] = ffma2(w0.y, xv.y, acc[0][b]);
            acc[1][b] = ffma2(w1.x, xv.x, acc[1][b]);
            acc[1][b] = ffma2(w1.y, xv.y, acc[1][b]);
            acc[2][b] = ffma2(w2.x, xv.x, acc[2][b]);
            acc[2][b] = ffma2(w2.y, xv.y, acc[2][b]);
            acc[3][b] = ffma2(w3.x, xv.x, acc[3][b]);
            acc[3][b] = ffma2(w3.y, xv.y, acc[3][b]);
        }
    }

#pragma unroll
    for (int r = 0; r < 4; r++) {
        float res = 0.f;
#pragma unroll
        for (int b = 0; b < 16; b++) {
            float v = ull_lo(acc[r][b]) + ull_hi(acc[r][b]);
            v += __shfl_xor_sync(0xffffffffu, v, 16);
            v += __shfl_xor_sync(0xffffffffu, v, 8);
            v += __shfl_xor_sync(0xffffffffu, v, 4);
            v += __shfl_xor_sync(0xffffffffu, v, 2);
            v += __shfl_xor_sync(0xffffffffu, v, 1);
            if (lane == b) res = v;
        }
        if (lane < 16) dst[(size_t)lane * stride + rbase + r] = res;
    }
}

// ---------------------------------------------------------------------------
// Kernel 2: RoPE on q and new k (interleaved pairs).
// ---------------------------------------------------------------------------
__global__ void k_rope(const float* __restrict__ fc, const float* __restrict__ fs)
{
    const int t = blockIdx.x * blockDim.x + threadIdx.x;
    float* base; int idx;
    if (t < BSZ * NH * 64) { base = g_q; idx = t; }
    else {
        idx = t - BSZ * NH * 64;
        if (idx >= BSZ * NKV * 64) return;
        base = g_k;
    }
    const int i = idx & 63;
    const float c = fc[i], s = fs[i];
    const float a  = base[2 * idx];
    const float bb = base[2 * idx + 1];
    base[2 * idx]     = a * c - bb * s;
    base[2 * idx + 1] = a * s + bb * c;
}

// ---------------------------------------------------------------------------
// Kernel 3: split-KV attention partials.
// grid = (NSPLIT, NKV, BSZ) = 2048 blocks, 256 threads.
// Phase A: warp-per-position K dot (4 GQA heads jointly, 9-shuffle reduce).
// Phase C: warp-per-position float4 V stream, per-lane float4 accumulators,
//          8-warp smem reduction.  Each K/V row touched exactly once.
// ---------------------------------------------------------------------------
__global__ void __launch_bounds__(256) k_attn(
    const float* __restrict__ cache_k,
    const float* __restrict__ cache_v,
    const int*   __restrict__ sp_ptr)
{
    const int split = blockIdx.x;
    const int hk    = blockIdx.y;
    const int b     = blockIdx.z;
    const int sp    = load_sp(sp_ptr);
    const int pos0  = split * SCHUNK;
    const int tid   = threadIdx.x;
    const int lane  = tid & 31;
    const int warp  = tid >> 5;

    __shared__ float  sc[4][SCHUNK];        // scores -> exp'd probs (4 KB)
    __shared__ float4 red4[8][4][32];       // per-warp partial O (16 KB)
    __shared__ float  redm[4][8];
    __shared__ float  redl[4][8];
    __shared__ float  fm[4];

    // Per-lane q fragments: 4 heads x float4 at dims [lane*4, lane*4+3]
    float4 ql[4];
#pragma unroll
    for (int j = 0; j < 4; j++)
        ql[j] = *reinterpret_cast<const float4*>(
            g_q + (size_t)b * DIM + (hk * 4 + j) * HD + lane * 4);

    // ---- Phase A: scores (stream K chunk once) ----
    const size_t kb = (size_t)b * MSL * KVROW + (size_t)hk * HD;
    for (int p = warp; p < SCHUNK; p += 8) {
        const int pos = pos0 + p;
        float4 k4;
        if (pos < sp)
            k4 = *reinterpret_cast<const float4*>(
                cache_k + kb + (size_t)pos * KVROW + lane * 4);
        else if (pos == sp)
            k4 = *reinterpret_cast<const float4*>(
                g_k + (b * NKV + hk) * HD + lane * 4);
        else
            k4 = make_float4(0.f, 0.f, 0.f, 0.f);

        float d0 = k4.x*ql[0].x + k4.y*ql[0].y + k4.z*ql[0].z + k4.w*ql[0].w;
        float d1 = k4.x*ql[1].x + k4.y*ql[1].y + k4.z*ql[1].z + k4.w*ql[1].w;
        float d2 = k4.x*ql[2].x + k4.y*ql[2].y + k4.z*ql[2].z + k4.w*ql[2].w;
        float d3 = k4.x*ql[3].x + k4.y*ql[3].y + k4.z*ql[3].z + k4.w*ql[3].w;

        // joint 4-value warp reduce in 9 shuffles; lane l ends with sum(d_{l&3})
        d0 += __shfl_xor_sync(0xffffffffu, d0, 1);
        d1 += __shfl_xor_sync(0xffffffffu, d1, 1);
        d2 += __shfl_xor_sync(0xffffffffu, d2, 1);
        d3 += __shfl_xor_sync(0xffffffffu, d3, 1);
        float aa = (lane & 1) ? d1 : d0;
        float bb = (lane & 1) ? d3 : d2;
        aa += __shfl_xor_sync(0xffffffffu, aa, 2);
        bb += __shfl_xor_sync(0xffffffffu, bb, 2);
        float cc = (lane & 2) ? bb : aa;
        cc += __shfl_xor_sync(0xffffffffu, cc, 4);
        cc += __shfl_xor_sync(0xffffffffu, cc, 8);
        cc += __shfl_xor_sync(0xffffffffu, cc, 16);
        if (lane < 4) sc[lane][p] = (pos <= sp) ? cc * SCALE : -1e30f;
    }
    __syncthreads();

    // ---- Phase B: chunk max ----
    float lm[4] = {-1e30f, -1e30f, -1e30f, -1e30f};
    for (int p = tid; p < SCHUNK; p += 256) {
#pragma unroll
        for (int h = 0; h < 4; h++) lm[h] = fmaxf(lm[h], sc[h][p]);
    }
#pragma unroll
    for (int h = 0; h < 4; h++) {
        float v = lm[h];
        v = fmaxf(v, __shfl_xor_sync(0xffffffffu, v, 16));
        v = fmaxf(v, __shfl_xor_sync(0xffffffffu, v, 8));
        v = fmaxf(v, __shfl_xor_sync(0xffffffffu, v, 4));
        v = fmaxf(v, __shfl_xor_sync(0xffffffffu, v, 2));
        v = fmaxf(v, __shfl_xor_sync(0xffffffffu, v, 1));
        if (lane == 0) redm[h][warp] = v;
    }
    __syncthreads();
    if (tid < 4) {
        float m = redm[tid][0];
#pragma unroll
        for (int w = 1; w < 8; w++) m = fmaxf(m, redm[tid][w]);
        fm[tid] = m;
    }
    __syncthreads();

    // ---- exp + row-sum ----
    float ll[4] = {0.f, 0.f, 0.f, 0.f};
    for (int p = tid; p < SCHUNK; p += 256) {
#pragma unroll
        for (int h = 0; h < 4; h++) {
            const float e = __expf(sc[h][p] - fm[h]);
            sc[h][p] = e;
            ll[h] += e;
        }
    }
#pragma unroll
    for (int h = 0; h < 4; h++) {
        float v = ll[h];
        v += __shfl_xor_sync(0xffffffffu, v, 16);
        v += __shfl_xor_sync(0xffffffffu, v, 8);
        v += __shfl_xor_sync(0xffffffffu, v, 4);
        v += __shfl_xor_sync(0xffffffffu, v, 2);
        v += __shfl_xor_sync(0xffffffffu, v, 1);
        if (lane == 0) redl[h][warp] = v;
    }
    __syncthreads();

    const size_t pi = (size_t)(b * NKV + hk) * NSPLIT + split;
    if (tid < 4) {
        float s = 0.f;
#pragma unroll
        for (int w = 0; w < 8; w++) s += redl[tid][w];
        g_m[pi * 4 + tid] = fm[tid];
        g_l[pi * 4 + tid] = s;
    }
    __syncthreads();   // sc[] fully exp'd before phase C reads it

    // ---- Phase C: warp-per-position V stream (float4), 4 heads per lane ----
    float4 a0 = {0,0,0,0}, a1 = {0,0,0,0}, a2 = {0,0,0,0}, a3 = {0,0,0,0};
    const float4 gv4 = *reinterpret_cast<const float4*>(
        g_v + (b * NKV + hk) * HD + lane * 4);
    const float* vb = cache_v + (size_t)b * MSL * KVROW + (size_t)hk * HD + lane * 4;
    for (int p = warp; p < SCHUNK; p += 8) {
        const int pos = pos0 + p;
        const float4 v4 = (pos == sp) ? gv4
            : *reinterpret_cast<const float4*>(vb + (size_t)pos * KVROW);
        const float p0 = sc[0][p], p1 = sc[1][p], p2 = sc[2][p], p3 = sc[3][p];
        a0.x = fmaf(p0, v4.x, a0.x); a0.y = fmaf(p0, v4.y, a0.y);
        a0.z = fmaf(p0, v4.z, a0.z); a0.w = fmaf(p0, v4.w, a0.w);
        a1.x = fmaf(p1, v4.x, a1.x); a1.y = fmaf(p1, v4.y, a1.y);
        a1.z = fmaf(p1, v4.z, a1.z); a1.w = fmaf(p1, v4.w, a1.w);
        a2.x = fmaf(p2, v4.x, a2.x); a2.y = fmaf(p2, v4.y, a2.y);
        a2.z = fmaf(p2, v4.z, a2.z); a2.w = fmaf(p2, v4.w, a2.w);
        a3.x = fmaf(p3, v4.x, a3.x); a3.y = fmaf(p3, v4.y, a3.y);
        a3.z = fmaf(p3, v4.z, a3.z); a3.w = fmaf(p3, v4.w, a3.w);
    }
    red4[warp][0][lane] = a0;
    red4[warp][1][lane] = a1;
    red4[warp][2][lane] = a2;
    red4[warp][3][lane] = a3;
    __syncthreads();

    // 8-warp reduction: 512 outputs (4 heads x 128 dims), 2 per thread.
    const float* redf = reinterpret_cast<const float*>(red4);
    float* op = g_op + pi * 4 * HD;
    for (int o = tid; o < 4 * HD; o += 256) {
        float s = 0.f;
#pragma unroll
        for (int w = 0; w < 8; w++) s += redf[w * 512 + o];
        op[o] = s;
    }
}

// ---------------------------------------------------------------------------
// Kernel 4: combine split partials into g_attn.  512 blocks x 128 threads.
// ---------------------------------------------------------------------------
__global__ void k_combine()
{
    const int bh = blockIdx.x;          // b*32 + h
    const int d  = threadIdx.x;
    const int b  = bh >> 5, h = bh & 31;
    const int hk = h >> 2, j = h & 3;
    const int base = (b * NKV + hk) * NSPLIT;

    float M = -1e30f;
#pragma unroll
    for (int s = 0; s < NSPLIT; s++) M = fmaxf(M, g_m[(base + s) * 4 + j]);
    float den = 0.f, o = 0.f;
#pragma unroll
    for (int s = 0; s < NSPLIT; s++) {
        const float w = __expf(g_m[(base + s) * 4 + j] - M);
        den += g_l[(base + s) * 4 + j] * w;
        o   += g_op[((size_t)(base + s) * 4 + j) * HD + d] * w;
    }
    g_attn[b * DIM + h * HD + d] = o / den;
}

// ---------------------------------------------------------------------------
// Kernel 5: output GEMV over wo with packed f32x2 accumulation.
// ---------------------------------------------------------------------------
__global__ void __launch_bounds__(256) k_gemv_out(
    const float* __restrict__ wo, float* __restrict__ out)
{
    const int gw   = (blockIdx.x * blockDim.x + threadIdx.x) >> 5;
    const int lane = threadIdx.x & 31;
    const int r0   = gw * 4;

    const float* w0p = wo + (size_t)(r0 + 0) * DIM;
    const float* w1p = wo + (size_t)(r0 + 1) * DIM;
    const float* w2p = wo + (size_t)(r0 + 2) * DIM;
    const float* w3p = wo + (size_t)(r0 + 3) * DIM;

    unsigned long long acc[4][16];
#pragma unroll
    for (int r = 0; r < 4; r++)
#pragma unroll
        for (int b = 0; b < 16; b++) acc[r][b] = 0ull;

    const int off = lane * 4;
    for (int c = 0; c < DIM; c += 128) {
        const ulonglong2 w0 = *reinterpret_cast<const ulonglong2*>(w0p + c + off);
        const ulonglong2 w1 = *reinterpret_cast<const ulonglong2*>(w1p + c + off);
        const ulonglong2 w2 = *reinterpret_cast<const ulonglong2*>(w2p + c + off);
        const ulonglong2 w3 = *reinterpret_cast<const ulonglong2*>(w3p + c + off);
#pragma unroll
        for (int b = 0; b < 16; b++) {
            const ulonglong2 xv = *reinterpret_cast<const ulonglong2*>(
                g_attn + (size_t)b * DIM + c + off);
            acc[0][b] = ffma2(w0.x, xv.x, acc[0][b]);
            acc[0][b] = ffma2(w0.y, xv.y, acc[0][b]);
            acc[1][b] = ffma2(w1.x, xv.x, acc[1][b]);
            acc[1][b] = ffma2(w1.y, xv.y, acc[1][b]);
            acc[2][b] = ffma2(w2.x, xv.x, acc[2][b]);
            acc[2][b] = ffma2(w2.y, xv.y, acc[2][b]);
            acc[3][b] = ffma2(w3.x, xv.x, acc[3][b]);
            acc[3][b] = ffma2(w3.y, xv.y, acc[3][b]);
        }
    }

#pragma unroll
    for (int r = 0; r < 4; r++) {
        float res = 0.f;
#pragma unroll
        for (int b = 0; b < 16; b++) {
            float v = ull_lo(acc[r][b]) + ull_hi(acc[r][b]);
            v += __shfl_xor_sync(0xffffffffu, v, 16);
            v += __shfl_xor_sync(0xffffffffu, v, 8);
            v += __shfl_xor_sync(0xffffffffu, v, 4);
            v += __shfl_xor_sync(0xffffffffu, v, 2);
            v += __shfl_xor_sync(0xffffffffu, v, 1);
            if (lane == b) res = v;
        }
        if (lane < 16) out[(size_t)lane * DIM + r0 + r] = res;
    }
}

// ---------------------------------------------------------------------------
// Launch: inputs are (x, wq, wk, wv, wo, cache_k, cache_v, fcos, fsin, start_pos)
// ---------------------------------------------------------------------------
extern "C" void kernel_launch(void* const* d_in, const int* in_sizes, int n_in,
                              void* d_out, int out_size)
{
    const float* x  = (const float*)d_in[0];
    const float* wq = (const float*)d_in[1];
    const float* wk = (const float*)d_in[2];
    const float* wv = (const float*)d_in[3];
    const float* wo = (const float*)d_in[4];
    const float* ck = (const float*)d_in[5];
    const float* cv = (const float*)d_in[6];
    const float* fc = (const float*)d_in[7];
    const float* fs = (const float*)d_in[8];
    const int*   sp = (const int*)d_in[9];
    float* out = (float*)d_out;

    k_gemv_qkv<<<192, 256>>>(x, wq, wk, wv);
    k_rope<<<160, 256>>>(fc, fs);
    dim3 ag(NSPLIT, NKV, BSZ);
    k_attn<<<ag, 256>>>(ck, cv, sp);
    k_combine<<<BSZ * NH, HD>>>();
    k_gemv_out<<<128, 256>>>(wo, out);
}

// round 7
// speedup vs baseline: 1.3319x; 1.2252x over previous
#include <cuda_runtime.h>
#include <cuda_bf16.h>
#include <cstdint>

// Problem constants (fixed by the dataset).
#define BSZ     16
#define DIM     4096
#define NH      32
#define NKV     8
#define HD      128
#define MSL     4096
#define NSPLIT  16
#define SCHUNK  256          // MSL / NSPLIT
#define KVROW   (NKV * HD)   // 1024 floats per cache position
#define SCALE   0.08838834764831845f   // 1/sqrt(128)
#define NROWS   6144         // 4096 q + 1024 k + 1024 v

// ---------------------------------------------------------------------------
// Scratch (no allocations allowed -> __device__ globals)
// ---------------------------------------------------------------------------
__device__ __align__(16) float g_q[BSZ * NH * HD];
__device__ __align__(16) float g_k[BSZ * NKV * HD];
__device__ __align__(16) float g_v[BSZ * NKV * HD];
__device__ __align__(16) float g_p [2 * NROWS * BSZ];     // qkv col-split partials
__device__ __align__(16) float g_po[2 * DIM   * BSZ];     // out  col-split partials
__device__ __align__(16) float g_op[BSZ * NKV * NSPLIT * 4 * HD];
__device__ float g_m[BSZ * NKV * NSPLIT * 4];
__device__ float g_l[BSZ * NKV * NSPLIT * 4];
__device__ __align__(16) float g_attn[BSZ * DIM];

// start_pos may arrive as int32/int64/float32 -> defensive decode
__device__ __forceinline__ int load_sp(const int* p) {
    int v = *p;
    if (v < 0 || v >= 1000000) v = (int)__int_as_float(v);
    return v;
}

// Packed fp32x2 FMA (sm_100a+)
__device__ __forceinline__ unsigned long long ffma2(
    unsigned long long a, unsigned long long b, unsigned long long c)
{
    unsigned long long d;
    asm("fma.rn.f32x2 %0, %1, %2, %3;" : "=l"(d) : "l"(a), "l"(b), "l"(c));
    return d;
}
__device__ __forceinline__ float ull_lo(unsigned long long v) {
    return __uint_as_float((unsigned)(v & 0xffffffffull));
}
__device__ __forceinline__ float ull_hi(unsigned long long v) {
    return __uint_as_float((unsigned)(v >> 32));
}

// ---------------------------------------------------------------------------
// Kernel 1: QKV GEMV, occupancy-fixed.
// Warp = 4 rows x 8 batches x 2048 cols (half).  6144 warps -> 768 blocks.
// Partial per (colsplit,row,batch) -> g_p; combined in k_fuse.
// ---------------------------------------------------------------------------
__global__ void __launch_bounds__(256, 2) k_gemv_qkv(
    const float* __restrict__ x,
    const float* __restrict__ wq,
    const float* __restrict__ wk,
    const float* __restrict__ wv)
{
    const int gw   = (blockIdx.x * blockDim.x + threadIdx.x) >> 5;
    const int lane = threadIdx.x & 31;
    const int rg   = gw >> 2;            // row group 0..1535
    const int bh   = gw & 1;             // batch half
    const int cs   = (gw >> 1) & 1;      // column split
    const int r0   = rg * 4;             // global row base 0..6143
    const int b0   = bh * 8;
    const int c0   = cs * 2048;

    const float* W; int rbase;
    if (r0 < 4096)      { W = wq; rbase = r0;        }
    else if (r0 < 5120) { W = wk; rbase = r0 - 4096; }
    else                { W = wv; rbase = r0 - 5120; }

    const float* w0p = W + (size_t)(rbase + 0) * DIM + c0;
    const float* w1p = W + (size_t)(rbase + 1) * DIM + c0;
    const float* w2p = W + (size_t)(rbase + 2) * DIM + c0;
    const float* w3p = W + (size_t)(rbase + 3) * DIM + c0;
    const float* xp  = x + (size_t)b0 * DIM + c0;

    unsigned long long acc[4][8];
#pragma unroll
    for (int r = 0; r < 4; r++)
#pragma unroll
        for (int b = 0; b < 8; b++) acc[r][b] = 0ull;

    const int off = lane * 4;
    for (int c = 0; c < 2048; c += 128) {
        const ulonglong2 w0 = *reinterpret_cast<const ulonglong2*>(w0p + c + off);
        const ulonglong2 w1 = *reinterpret_cast<const ulonglong2*>(w1p + c + off);
        const ulonglong2 w2 = *reinterpret_cast<const ulonglong2*>(w2p + c + off);
        const ulonglong2 w3 = *reinterpret_cast<const ulonglong2*>(w3p + c + off);
#pragma unroll
        for (int b = 0; b < 8; b++) {
            const ulonglong2 xv =
                *reinterpret_cast<const ulonglong2*>(xp + (size_t)b * DIM + c + off);
            acc[0][b] = ffma2(w0.x, xv.x, acc[0][b]);
            acc[0][b] = ffma2(w0.y, xv.y, acc[0][b]);
            acc[1][b] = ffma2(w1.x, xv.x, acc[1][b]);
            acc[1][b] = ffma2(w1.y, xv.y, acc[1][b]);
            acc[2][b] = ffma2(w2.x, xv.x, acc[2][b]);
            acc[2][b] = ffma2(w2.y, xv.y, acc[2][b]);
            acc[3][b] = ffma2(w3.x, xv.x, acc[3][b]);
            acc[3][b] = ffma2(w3.y, xv.y, acc[3][b]);
        }
    }

#pragma unroll
    for (int r = 0; r < 4; r++) {
        float res = 0.f;
#pragma unroll
        for (int b = 0; b < 8; b++) {
            float v = ull_lo(acc[r][b]) + ull_hi(acc[r][b]);
            v += __shfl_xor_sync(0xffffffffu, v, 16);
            v += __shfl_xor_sync(0xffffffffu, v, 8);
            v += __shfl_xor_sync(0xffffffffu, v, 4);
            v += __shfl_xor_sync(0xffffffffu, v, 2);
            v += __shfl_xor_sync(0xffffffffu, v, 1);
            if (lane == b) res = v;
        }
        if (lane < 8)
            g_p[((size_t)cs * NROWS + r0 + r) * BSZ + b0 + lane] = res;
    }
}

// ---------------------------------------------------------------------------
// Kernel 2: combine col-split partials + RoPE, write g_q/g_k/g_v.
// q pairs: 16*2048, k pairs: 16*512, v elems: 16*1024 -> 57344 threads.
// ---------------------------------------------------------------------------
__global__ void k_fuse(const float* __restrict__ fc, const float* __restrict__ fs)
{
    const int t = blockIdx.x * blockDim.x + threadIdx.x;
    if (t < 32768) {                       // q pairs
        const int b = t >> 11, j = t & 2047;
        const int row = 2 * j;
        const float a  = g_p[(size_t)row * BSZ + b] + g_p[((size_t)NROWS + row) * BSZ + b];
        const float bb = g_p[(size_t)(row + 1) * BSZ + b] + g_p[((size_t)NROWS + row + 1) * BSZ + b];
        const float c = fc[j & 63], s = fs[j & 63];
        g_q[(size_t)b * DIM + row]     = a * c - bb * s;
        g_q[(size_t)b * DIM + row + 1] = a * s + bb * c;
    } else if (t < 40960) {                // k pairs
        const int u = t - 32768;
        const int b = u >> 9, j = u & 511;
        const int row = 4096 + 2 * j;
        const float a  = g_p[(size_t)row * BSZ + b] + g_p[((size_t)NROWS + row) * BSZ + b];
        const float bb = g_p[(size_t)(row + 1) * BSZ + b] + g_p[((size_t)NROWS + row + 1) * BSZ + b];
        const float c = fc[j & 63], s = fs[j & 63];
        g_k[(size_t)b * KVROW + 2 * j]     = a * c - bb * s;
        g_k[(size_t)b * KVROW + 2 * j + 1] = a * s + bb * c;
    } else if (t < 57344) {                // v elements
        const int u = t - 40960;
        const int b = u >> 10, e = u & 1023;
        const int row = 5120 + e;
        g_v[(size_t)b * KVROW + e] =
            g_p[(size_t)row * BSZ + b] + g_p[((size_t)NROWS + row) * BSZ + b];
    }
}

// ---------------------------------------------------------------------------
// Kernel 3: split-KV attention partials (unchanged from R5).
// ---------------------------------------------------------------------------
__global__ void __launch_bounds__(256) k_attn(
    const float* __restrict__ cache_k,
    const float* __restrict__ cache_v,
    const int*   __restrict__ sp_ptr)
{
    const int split = blockIdx.x;
    const int hk    = blockIdx.y;
    const int b     = blockIdx.z;
    const int sp    = load_sp(sp_ptr);
    const int pos0  = split * SCHUNK;
    const int tid   = threadIdx.x;
    const int lane  = tid & 31;
    const int warp  = tid >> 5;

    __shared__ float  sc[4][SCHUNK];
    __shared__ float4 red4[8][4][32];
    __shared__ float  redm[4][8];
    __shared__ float  redl[4][8];
    __shared__ float  fm[4];

    float4 ql[4];
#pragma unroll
    for (int j = 0; j < 4; j++)
        ql[j] = *reinterpret_cast<const float4*>(
            g_q + (size_t)b * DIM + (hk * 4 + j) * HD + lane * 4);

    // ---- Phase A: scores ----
    const size_t kb = (size_t)b * MSL * KVROW + (size_t)hk * HD;
    for (int p = warp; p < SCHUNK; p += 8) {
        const int pos = pos0 + p;
        float4 k4;
        if (pos < sp)
            k4 = *reinterpret_cast<const float4*>(
                cache_k + kb + (size_t)pos * KVROW + lane * 4);
        else if (pos == sp)
            k4 = *reinterpret_cast<const float4*>(
                g_k + (b * NKV + hk) * HD + lane * 4);
        else
            k4 = make_float4(0.f, 0.f, 0.f, 0.f);

        float d0 = k4.x*ql[0].x + k4.y*ql[0].y + k4.z*ql[0].z + k4.w*ql[0].w;
        float d1 = k4.x*ql[1].x + k4.y*ql[1].y + k4.z*ql[1].z + k4.w*ql[1].w;
        float d2 = k4.x*ql[2].x + k4.y*ql[2].y + k4.z*ql[2].z + k4.w*ql[2].w;
        float d3 = k4.x*ql[3].x + k4.y*ql[3].y + k4.z*ql[3].z + k4.w*ql[3].w;

        d0 += __shfl_xor_sync(0xffffffffu, d0, 1);
        d1 += __shfl_xor_sync(0xffffffffu, d1, 1);
        d2 += __shfl_xor_sync(0xffffffffu, d2, 1);
        d3 += __shfl_xor_sync(0xffffffffu, d3, 1);
        float aa = (lane & 1) ? d1 : d0;
        float bb = (lane & 1) ? d3 : d2;
        aa += __shfl_xor_sync(0xffffffffu, aa, 2);
        bb += __shfl_xor_sync(0xffffffffu, bb, 2);
        float cc = (lane & 2) ? bb : aa;
        cc += __shfl_xor_sync(0xffffffffu, cc, 4);
        cc += __shfl_xor_sync(0xffffffffu, cc, 8);
        cc += __shfl_xor_sync(0xffffffffu, cc, 16);
        if (lane < 4) sc[lane][p] = (pos <= sp) ? cc * SCALE : -1e30f;
    }
    __syncthreads();

    // ---- Phase B: chunk max ----
    float lm[4] = {-1e30f, -1e30f, -1e30f, -1e30f};
    for (int p = tid; p < SCHUNK; p += 256) {
#pragma unroll
        for (int h = 0; h < 4; h++) lm[h] = fmaxf(lm[h], sc[h][p]);
    }
#pragma unroll
    for (int h = 0; h < 4; h++) {
        float v = lm[h];
        v = fmaxf(v, __shfl_xor_sync(0xffffffffu, v, 16));
        v = fmaxf(v, __shfl_xor_sync(0xffffffffu, v, 8));
        v = fmaxf(v, __shfl_xor_sync(0xffffffffu, v, 4));
        v = fmaxf(v, __shfl_xor_sync(0xffffffffu, v, 2));
        v = fmaxf(v, __shfl_xor_sync(0xffffffffu, v, 1));
        if (lane == 0) redm[h][warp] = v;
    }
    __syncthreads();
    if (tid < 4) {
        float m = redm[tid][0];
#pragma unroll
        for (int w = 1; w < 8; w++) m = fmaxf(m, redm[tid][w]);
        fm[tid] = m;
    }
    __syncthreads();

    // ---- exp + row-sum ----
    float ll[4] = {0.f, 0.f, 0.f, 0.f};
    for (int p = tid; p < SCHUNK; p += 256) {
#pragma unroll
        for (int h = 0; h < 4; h++) {
            const float e = __expf(sc[h][p] - fm[h]);
            sc[h][p] = e;
            ll[h] += e;
        }
    }
#pragma unroll
    for (int h = 0; h < 4; h++) {
        float v = ll[h];
        v += __shfl_xor_sync(0xffffffffu, v, 16);
        v += __shfl_xor_sync(0xffffffffu, v, 8);
        v += __shfl_xor_sync(0xffffffffu, v, 4);
        v += __shfl_xor_sync(0xffffffffu, v, 2);
        v += __shfl_xor_sync(0xffffffffu, v, 1);
        if (lane == 0) redl[h][warp] = v;
    }
    __syncthreads();

    const size_t pi = (size_t)(b * NKV + hk) * NSPLIT + split;
    if (tid < 4) {
        float s = 0.f;
#pragma unroll
        for (int w = 0; w < 8; w++) s += redl[tid][w];
        g_m[pi * 4 + tid] = fm[tid];
        g_l[pi * 4 + tid] = s;
    }
    __syncthreads();

    // ---- Phase C: warp-per-position V stream ----
    float4 a0 = {0,0,0,0}, a1 = {0,0,0,0}, a2 = {0,0,0,0}, a3 = {0,0,0,0};
    const float4 gv4 = *reinterpret_cast<const float4*>(
        g_v + (b * NKV + hk) * HD + lane * 4);
    const float* vb = cache_v + (size_t)b * MSL * KVROW + (size_t)hk * HD + lane * 4;
    for (int p = warp; p < SCHUNK; p += 8) {
        const int pos = pos0 + p;
        const float4 v4 = (pos == sp) ? gv4
            : *reinterpret_cast<const float4*>(vb + (size_t)pos * KVROW);
        const float p0 = sc[0][p], p1 = sc[1][p], p2 = sc[2][p], p3 = sc[3][p];
        a0.x = fmaf(p0, v4.x, a0.x); a0.y = fmaf(p0, v4.y, a0.y);
        a0.z = fmaf(p0, v4.z, a0.z); a0.w = fmaf(p0, v4.w, a0.w);
        a1.x = fmaf(p1, v4.x, a1.x); a1.y = fmaf(p1, v4.y, a1.y);
        a1.z = fmaf(p1, v4.z, a1.z); a1.w = fmaf(p1, v4.w, a1.w);
        a2.x = fmaf(p2, v4.x, a2.x); a2.y = fmaf(p2, v4.y, a2.y);
        a2.z = fmaf(p2, v4.z, a2.z); a2.w = fmaf(p2, v4.w, a2.w);
        a3.x = fmaf(p3, v4.x, a3.x); a3.y = fmaf(p3, v4.y, a3.y);
        a3.z = fmaf(p3, v4.z, a3.z); a3.w = fmaf(p3, v4.w, a3.w);
    }
    red4[warp][0][lane] = a0;
    red4[warp][1][lane] = a1;
    red4[warp][2][lane] = a2;
    red4[warp][3][lane] = a3;
    __syncthreads();

    const float* redf = reinterpret_cast<const float*>(red4);
    float* op = g_op + pi * 4 * HD;
    for (int o = tid; o < 4 * HD; o += 256) {
        float s = 0.f;
#pragma unroll
        for (int w = 0; w < 8; w++) s += redf[w * 512 + o];
        op[o] = s;
    }
}

// ---------------------------------------------------------------------------
// Kernel 4: combine split partials into g_attn.
// ---------------------------------------------------------------------------
__global__ void k_combine()
{
    const int bh = blockIdx.x;
    const int d  = threadIdx.x;
    const int b  = bh >> 5, h = bh & 31;
    const int hk = h >> 2, j = h & 3;
    const int base = (b * NKV + hk) * NSPLIT;

    float M = -1e30f;
#pragma unroll
    for (int s = 0; s < NSPLIT; s++) M = fmaxf(M, g_m[(base + s) * 4 + j]);
    float den = 0.f, o = 0.f;
#pragma unroll
    for (int s = 0; s < NSPLIT; s++) {
        const float w = __expf(g_m[(base + s) * 4 + j] - M);
        den += g_l[(base + s) * 4 + j] * w;
        o   += g_op[((size_t)(base + s) * 4 + j) * HD + d] * w;
    }
    g_attn[b * DIM + h * HD + d] = o / den;
}

// ---------------------------------------------------------------------------
// Kernel 5: output GEMV, occupancy-fixed (same scheme as kernel 1).
// 4096 warps -> 512 blocks; partials to g_po.
// ---------------------------------------------------------------------------
__global__ void __launch_bounds__(256, 2) k_gemv_out(
    const float* __restrict__ wo)
{
    const int gw   = (blockIdx.x * blockDim.x + threadIdx.x) >> 5;
    const int lane = threadIdx.x & 31;
    const int rg   = gw >> 2;
    const int bh   = gw & 1;
    const int cs   = (gw >> 1) & 1;
    const int r0   = rg * 4;
    const int b0   = bh * 8;
    const int c0   = cs * 2048;

    const float* w0p = wo + (size_t)(r0 + 0) * DIM + c0;
    const float* w1p = wo + (size_t)(r0 + 1) * DIM + c0;
    const float* w2p = wo + (size_t)(r0 + 2) * DIM + c0;
    const float* w3p = wo + (size_t)(r0 + 3) * DIM + c0;
    const float* xp  = g_attn + (size_t)b0 * DIM + c0;

    unsigned long long acc[4][8];
#pragma unroll
    for (int r = 0; r < 4; r++)
#pragma unroll
        for (int b = 0; b < 8; b++) acc[r][b] = 0ull;

    const int off = lane * 4;
    for (int c = 0; c < 2048; c += 128) {
        const ulonglong2 w0 = *reinterpret_cast<const ulonglong2*>(w0p + c + off);
        const ulonglong2 w1 = *reinterpret_cast<const ulonglong2*>(w1p + c + off);
        const ulonglong2 w2 = *reinterpret_cast<const ulonglong2*>(w2p + c + off);
        const ulonglong2 w3 = *reinterpret_cast<const ulonglong2*>(w3p + c + off);
#pragma unroll
        for (int b = 0; b < 8; b++) {
            const ulonglong2 xv =
                *reinterpret_cast<const ulonglong2*>(xp + (size_t)b * DIM + c + off);
            acc[0][b] = ffma2(w0.x, xv.x, acc[0][b]);
            acc[0][b] = ffma2(w0.y, xv.y, acc[0][b]);
            acc[1][b] = ffma2(w1.x, xv.x, acc[1][b]);
            acc[1][b] = ffma2(w1.y, xv.y, acc[1][b]);
            acc[2][b] = ffma2(w2.x, xv.x, acc[2][b]);
            acc[2][b] = ffma2(w2.y, xv.y, acc[2][b]);
            acc[3][b] = ffma2(w3.x, xv.x, acc[3][b]);
            acc[3][b] = ffma2(w3.y, xv.y, acc[3][b]);
        }
    }

#pragma unroll
    for (int r = 0; r < 4; r++) {
        float res = 0.f;
#pragma unroll
        for (int b = 0; b < 8; b++) {
            float v = ull_lo(acc[r][b]) + ull_hi(acc[r][b]);
            v += __shfl_xor_sync(0xffffffffu, v, 16);
            v += __shfl_xor_sync(0xffffffffu, v, 8);
            v += __shfl_xor_sync(0xffffffffu, v, 4);
            v += __shfl_xor_sync(0xffffffffu, v, 2);
            v += __shfl_xor_sync(0xffffffffu, v, 1);
            if (lane == b) res = v;
        }
        if (lane < 8)
            g_po[((size_t)cs * DIM + r0 + r) * BSZ + b0 + lane] = res;
    }
}

// ---------------------------------------------------------------------------
// Kernel 6: combine output col-split partials -> d_out.  65536 threads.
// ---------------------------------------------------------------------------
__global__ void k_ocomb(float* __restrict__ out)
{
    const int t = blockIdx.x * blockDim.x + threadIdx.x;
    const int b = t >> 12, row = t & 4095;
    out[(size_t)b * DIM + row] =
        g_po[(size_t)row * BSZ + b] + g_po[((size_t)DIM + row) * BSZ + b];
}

// ---------------------------------------------------------------------------
// Launch: inputs are (x, wq, wk, wv, wo, cache_k, cache_v, fcos, fsin, start_pos)
// ---------------------------------------------------------------------------
extern "C" void kernel_launch(void* const* d_in, const int* in_sizes, int n_in,
                              void* d_out, int out_size)
{
    const float* x  = (const float*)d_in[0];
    const float* wq = (const float*)d_in[1];
    const float* wk = (const float*)d_in[2];
    const float* wv = (const float*)d_in[3];
    const float* wo = (const float*)d_in[4];
    const float* ck = (const float*)d_in[5];
    const float* cv = (const float*)d_in[6];
    const float* fc = (const float*)d_in[7];
    const float* fs = (const float*)d_in[8];
    const int*   sp = (const int*)d_in[9];
    float* out = (float*)d_out;

    k_gemv_qkv<<<768, 256>>>(x, wq, wk, wv);
    k_fuse<<<224, 256>>>(fc, fs);
    dim3 ag(NSPLIT, NKV, BSZ);
    k_attn<<<ag, 256>>>(ck, cv, sp);
    k_combine<<<BSZ * NH, HD>>>();
    k_gemv_out<<<512, 256>>>(wo);
    k_ocomb<<<256, 256>>>(out);
}

// round 9
// speedup vs baseline: 1.4495x; 1.0883x over previous
#include <cuda_runtime.h>
#include <cuda_bf16.h>
#include <cstdint>

// Problem constants (fixed by the dataset).
#define BSZ     16
#define DIM     4096
#define NH      32
#define NKV     8
#define HD      128
#define MSL     4096
#define NSPLIT  16
#define SCHUNK  256          // MSL / NSPLIT
#define KVROW   (NKV * HD)   // 1024 floats per cache position
#define SCALE   0.08838834764831845f   // 1/sqrt(128)
#define NROWS   6144         // 4096 q + 1024 k + 1024 v

// ---------------------------------------------------------------------------
// Scratch
// ---------------------------------------------------------------------------
__device__ __align__(16) float g_q[BSZ * NH * HD];
__device__ __align__(16) float g_k[BSZ * NKV * HD];
__device__ __align__(16) float g_v[BSZ * NKV * HD];
__device__ __align__(16) float g_p [2 * NROWS * BSZ];
__device__ __align__(16) float g_po[2 * DIM   * BSZ];
__device__ __align__(16) float g_op[BSZ * NKV * NSPLIT * 4 * HD];
__device__ float g_m[BSZ * NKV * NSPLIT * 4];
__device__ float g_l[BSZ * NKV * NSPLIT * 4];
__device__ __align__(16) float g_attn[BSZ * DIM];

__device__ __forceinline__ int load_sp(const int* p) {
    int v = *p;
    if (v < 0 || v >= 1000000) v = (int)__int_as_float(v);
    return v;
}

__device__ __forceinline__ unsigned long long ffma2(
    unsigned long long a, unsigned long long b, unsigned long long c)
{
    unsigned long long d;
    asm("fma.rn.f32x2 %0, %1, %2, %3;" : "=l"(d) : "l"(a), "l"(b), "l"(c));
    return d;
}
__device__ __forceinline__ float ull_lo(unsigned long long v) {
    return __uint_as_float((unsigned)(v & 0xffffffffull));
}
__device__ __forceinline__ float ull_hi(unsigned long long v) {
    return __uint_as_float((unsigned)(v >> 32));
}

// Joint 4-head dot + 9-shuffle reduce; returns head-(lane&3) total in every lane.
__device__ __forceinline__ float dot4r(const float4 k4, const float4 ql[4], int lane)
{
    float d0 = k4.x*ql[0].x + k4.y*ql[0].y + k4.z*ql[0].z + k4.w*ql[0].w;
    float d1 = k4.x*ql[1].x + k4.y*ql[1].y + k4.z*ql[1].z + k4.w*ql[1].w;
    float d2 = k4.x*ql[2].x + k4.y*ql[2].y + k4.z*ql[2].z + k4.w*ql[2].w;
    float d3 = k4.x*ql[3].x + k4.y*ql[3].y + k4.z*ql[3].z + k4.w*ql[3].w;
    d0 += __shfl_xor_sync(0xffffffffu, d0, 1);
    d1 += __shfl_xor_sync(0xffffffffu, d1, 1);
    d2 += __shfl_xor_sync(0xffffffffu, d2, 1);
    d3 += __shfl_xor_sync(0xffffffffu, d3, 1);
    float aa = (lane & 1) ? d1 : d0;
    float bb = (lane & 1) ? d3 : d2;
    aa += __shfl_xor_sync(0xffffffffu, aa, 2);
    bb += __shfl_xor_sync(0xffffffffu, bb, 2);
    float cc = (lane & 2) ? bb : aa;
    cc += __shfl_xor_sync(0xffffffffu, cc, 4);
    cc += __shfl_xor_sync(0xffffffffu, cc, 8);
    cc += __shfl_xor_sync(0xffffffffu, cc, 16);
    return cc;
}

// ---------------------------------------------------------------------------
// Kernel 1: QKV GEMV.  Block = 16 rows, shared (batch-half, col-split).
// Warp = 2 rows x 8 batches x 2048 cols.  1536 blocks, 3 blocks/SM.
// ---------------------------------------------------------------------------
__global__ void __launch_bounds__(256, 3) k_gemv_qkv(
    const float* __restrict__ x,
    const float* __restrict__ wq,
    const float* __restrict__ wk,
    const float* __restrict__ wv)
{
    const int warp = threadIdx.x >> 5;
    const int lane = threadIdx.x & 31;
    const int cs   = blockIdx.x & 1;
    const int bh   = (blockIdx.x >> 1) & 1;
    const int rb   = blockIdx.x >> 2;          // 0..383
    const int r0   = rb * 16 + warp * 2;       // global row base
    const int b0   = bh * 8;
    const int c0   = cs * 2048;

    const float* W; int rbase;
    if (r0 < 4096)      { W = wq; rbase = r0;        }
    else if (r0 < 5120) { W = wk; rbase = r0 - 4096; }
    else                { W = wv; rbase = r0 - 5120; }

    const float* w0p = W + (size_t)(rbase + 0) * DIM + c0;
    const float* w1p = W + (size_t)(rbase + 1) * DIM + c0;
    const float* xp  = x + (size_t)b0 * DIM + c0;

    unsigned long long acc[2][8];
#pragma unroll
    for (int r = 0; r < 2; r++)
#pragma unroll
        for (int b = 0; b < 8; b++) acc[r][b] = 0ull;

    const int off = lane * 4;
    for (int c = 0; c < 2048; c += 128) {
        const ulonglong2 w0 = *reinterpret_cast<const ulonglong2*>(w0p + c + off);
        const ulonglong2 w1 = *reinterpret_cast<const ulonglong2*>(w1p + c + off);
#pragma unroll
        for (int b = 0; b < 8; b++) {
            const ulonglong2 xv =
                *reinterpret_cast<const ulonglong2*>(xp + (size_t)b * DIM + c + off);
            acc[0][b] = ffma2(w0.x, xv.x, acc[0][b]);
            acc[0][b] = ffma2(w0.y, xv.y, acc[0][b]);
            acc[1][b] = ffma2(w1.x, xv.x, acc[1][b]);
            acc[1][b] = ffma2(w1.y, xv.y, acc[1][b]);
        }
    }

#pragma unroll
    for (int r = 0; r < 2; r++) {
        float res = 0.f;
#pragma unroll
        for (int b = 0; b < 8; b++) {
            float v = ull_lo(acc[r][b]) + ull_hi(acc[r][b]);
            v += __shfl_xor_sync(0xffffffffu, v, 16);
            v += __shfl_xor_sync(0xffffffffu, v, 8);
            v += __shfl_xor_sync(0xffffffffu, v, 4);
            v += __shfl_xor_sync(0xffffffffu, v, 2);
            v += __shfl_xor_sync(0xffffffffu, v, 1);
            if (lane == b) res = v;
        }
        if (lane < 8)
            g_p[((size_t)cs * NROWS + r0 + r) * BSZ + b0 + lane] = res;
    }
}

// ---------------------------------------------------------------------------
// Kernel 2: combine col-split partials + RoPE.
// ---------------------------------------------------------------------------
__global__ void k_fuse(const float* __restrict__ fc, const float* __restrict__ fs)
{
    const int t = blockIdx.x * blockDim.x + threadIdx.x;
    if (t < 32768) {                       // q pairs
        const int b = t >> 11, j = t & 2047;
        const int row = 2 * j;
        const float a  = g_p[(size_t)row * BSZ + b] + g_p[((size_t)NROWS + row) * BSZ + b];
        const float bb = g_p[(size_t)(row + 1) * BSZ + b] + g_p[((size_t)NROWS + row + 1) * BSZ + b];
        const float c = fc[j & 63], s = fs[j & 63];
        g_q[(size_t)b * DIM + row]     = a * c - bb * s;
        g_q[(size_t)b * DIM + row + 1] = a * s + bb * c;
    } else if (t < 40960) {                // k pairs
        const int u = t - 32768;
        const int b = u >> 9, j = u & 511;
        const int row = 4096 + 2 * j;
        const float a  = g_p[(size_t)row * BSZ + b] + g_p[((size_t)NROWS + row) * BSZ + b];
        const float bb = g_p[(size_t)(row + 1) * BSZ + b] + g_p[((size_t)NROWS + row + 1) * BSZ + b];
        const float c = fc[j & 63], s = fs[j & 63];
        g_k[(size_t)b * KVROW + 2 * j]     = a * c - bb * s;
        g_k[(size_t)b * KVROW + 2 * j + 1] = a * s + bb * c;
    } else if (t < 57344) {                // v elements
        const int u = t - 40960;
        const int b = u >> 10, e = u & 1023;
        const int row = 5120 + e;
        g_v[(size_t)b * KVROW + e] =
            g_p[(size_t)row * BSZ + b] + g_p[((size_t)NROWS + row) * BSZ + b];
    }
}

// ---------------------------------------------------------------------------
// Kernel 3: split-KV attention partials.
// Phase A: 4-way unrolled K stream with fused max-tracking (Phase B rescan gone).
// Phase C: 4-way unrolled V stream.
// ---------------------------------------------------------------------------
__global__ void __launch_bounds__(256) k_attn(
    const float* __restrict__ cache_k,
    const float* __restrict__ cache_v,
    const int*   __restrict__ sp_ptr)
{
    const int split = blockIdx.x;
    const int hk    = blockIdx.y;
    const int b     = blockIdx.z;
    const int sp    = load_sp(sp_ptr);
    const int pos0  = split * SCHUNK;
    const int tid   = threadIdx.x;
    const int lane  = tid & 31;
    const int warp  = tid >> 5;
    const bool pure = (pos0 + SCHUNK <= sp);   // whole chunk strictly before sp

    __shared__ float  sc[4][SCHUNK];
    __shared__ float4 red4[8][4][32];
    __shared__ float  redm[4][8];
    __shared__ float  redl[4][8];
    __shared__ float  fm[4];

    float4 ql[4];
#pragma unroll
    for (int j = 0; j < 4; j++)
        ql[j] = *reinterpret_cast<const float4*>(
            g_q + (size_t)b * DIM + (hk * 4 + j) * HD + lane * 4);

    // ---- Phase A: scores + running per-head max ----
    const size_t kb = (size_t)b * MSL * KVROW + (size_t)hk * HD;
    float lmax = -1e30f;                       // head = lane & 3
    if (pure) {
        const float* kp = cache_k + kb + (size_t)pos0 * KVROW + lane * 4;
        for (int p = warp; p < SCHUNK; p += 32) {
            const float4 kA = *reinterpret_cast<const float4*>(kp + (size_t)(p     ) * KVROW);
            const float4 kB = *reinterpret_cast<const float4*>(kp + (size_t)(p +  8) * KVROW);
            const float4 kC = *reinterpret_cast<const float4*>(kp + (size_t)(p + 16) * KVROW);
            const float4 kD = *reinterpret_cast<const float4*>(kp + (size_t)(p + 24) * KVROW);
            const float cA = dot4r(kA, ql, lane) * SCALE;
            const float cB = dot4r(kB, ql, lane) * SCALE;
            const float cC = dot4r(kC, ql, lane) * SCALE;
            const float cD = dot4r(kD, ql, lane) * SCALE;
            if (lane < 4) {
                sc[lane][p]      = cA;
                sc[lane][p +  8] = cB;
                sc[lane][p + 16] = cC;
                sc[lane][p + 24] = cD;
            }
            lmax = fmaxf(lmax, fmaxf(fmaxf(cA, cB), fmaxf(cC, cD)));
        }
    } else {
        for (int p = warp; p < SCHUNK; p += 8) {
            const int pos = pos0 + p;
            float4 k4;
            if (pos < sp)
                k4 = *reinterpret_cast<const float4*>(
                    cache_k + kb + (size_t)pos * KVROW + lane * 4);
            else if (pos == sp)
                k4 = *reinterpret_cast<const float4*>(
                    g_k + (b * NKV + hk) * HD + lane * 4);
            else
                k4 = make_float4(0.f, 0.f, 0.f, 0.f);
            const float cc  = dot4r(k4, ql, lane) * SCALE;
            const float val = (pos <= sp) ? cc : -1e30f;
            if (lane < 4) sc[lane][p] = val;
            lmax = fmaxf(lmax, val);
        }
    }
    if (lane < 4) redm[lane][warp] = lmax;
    __syncthreads();
    if (tid < 4) {
        float m = redm[tid][0];
#pragma unroll
        for (int w = 1; w < 8; w++) m = fmaxf(m, redm[tid][w]);
        fm[tid] = m;
    }
    __syncthreads();

    // ---- exp + row-sum ----
    float ll[4] = {0.f, 0.f, 0.f, 0.f};
    for (int p = tid; p < SCHUNK; p += 256) {
#pragma unroll
        for (int h = 0; h < 4; h++) {
            const float e = __expf(sc[h][p] - fm[h]);
            sc[h][p] = e;
            ll[h] += e;
        }
    }
#pragma unroll
    for (int h = 0; h < 4; h++) {
        float v = ll[h];
        v += __shfl_xor_sync(0xffffffffu, v, 16);
        v += __shfl_xor_sync(0xffffffffu, v, 8);
        v += __shfl_xor_sync(0xffffffffu, v, 4);
        v += __shfl_xor_sync(0xffffffffu, v, 2);
        v += __shfl_xor_sync(0xffffffffu, v, 1);
        if (lane == 0) redl[h][warp] = v;
    }
    __syncthreads();

    const size_t pi = (size_t)(b * NKV + hk) * NSPLIT + split;
    if (tid < 4) {
        float s = 0.f;
#pragma unroll
        for (int w = 0; w < 8; w++) s += redl[tid][w];
        g_m[pi * 4 + tid] = fm[tid];
        g_l[pi * 4 + tid] = s;
    }
    __syncthreads();

    // ---- Phase C: V stream ----
    float4 a0 = {0,0,0,0}, a1 = {0,0,0,0}, a2 = {0,0,0,0}, a3 = {0,0,0,0};
    const float* vb = cache_v + (size_t)b * MSL * KVROW + (size_t)hk * HD + lane * 4;
#define ACC4(PP, V4)                                                          \
    {   const float p0 = sc[0][PP], p1 = sc[1][PP],                           \
                    p2 = sc[2][PP], p3 = sc[3][PP];                           \
        a0.x = fmaf(p0, (V4).x, a0.x); a0.y = fmaf(p0, (V4).y, a0.y);         \
        a0.z = fmaf(p0, (V4).z, a0.z); a0.w = fmaf(p0, (V4).w, a0.w);         \
        a1.x = fmaf(p1, (V4).x, a1.x); a1.y = fmaf(p1, (V4).y, a1.y);         \
        a1.z = fmaf(p1, (V4).z, a1.z); a1.w = fmaf(p1, (V4).w, a1.w);         \
        a2.x = fmaf(p2, (V4).x, a2.x); a2.y = fmaf(p2, (V4).y, a2.y);         \
        a2.z = fmaf(p2, (V4).z, a2.z); a2.w = fmaf(p2, (V4).w, a2.w);         \
        a3.x = fmaf(p3, (V4).x, a3.x); a3.y = fmaf(p3, (V4).y, a3.y);         \
        a3.z = fmaf(p3, (V4).z, a3.z); a3.w = fmaf(p3, (V4).w, a3.w); }
    if (pure) {
        const float* vp = vb + (size_t)pos0 * KVROW;
        for (int p = warp; p < SCHUNK; p += 32) {
            const float4 vA = *reinterpret_cast<const float4*>(vp + (size_t)(p     ) * KVROW);
            const float4 vB = *reinterpret_cast<const float4*>(vp + (size_t)(p +  8) * KVROW);
            const float4 vC = *reinterpret_cast<const float4*>(vp + (size_t)(p + 16) * KVROW);
            const float4 vD = *reinterpret_cast<const float4*>(vp + (size_t)(p + 24) * KVROW);
            ACC4(p,      vA);
            ACC4(p +  8, vB);
            ACC4(p + 16, vC);
            ACC4(p + 24, vD);
        }
    } else {
        const float4 gv4 = *reinterpret_cast<const float4*>(
            g_v + (b * NKV + hk) * HD + lane * 4);
        for (int p = warp; p < SCHUNK; p += 8) {
            const int pos = pos0 + p;
            const float4 v4 = (pos == sp) ? gv4
                : *reinterpret_cast<const float4*>(vb + (size_t)pos * KVROW);
            ACC4(p, v4);
        }
    }
#undef ACC4
    red4[warp][0][lane] = a0;
    red4[warp][1][lane] = a1;
    red4[warp][2][lane] = a2;
    red4[warp][3][lane] = a3;
    __syncthreads();

    const float* redf = reinterpret_cast<const float*>(red4);
    float* op = g_op + pi * 4 * HD;
    for (int o = tid; o < 4 * HD; o += 256) {
        float s = 0.f;
#pragma unroll
        for (int w = 0; w < 8; w++) s += redf[w * 512 + o];
        op[o] = s;
    }
}

// ---------------------------------------------------------------------------
// Kernel 4: combine split partials into g_attn.
// ---------------------------------------------------------------------------
__global__ void k_combine()
{
    const int bh = blockIdx.x;
    const int d  = threadIdx.x;
    const int b  = bh >> 5, h = bh & 31;
    const int hk = h >> 2, j = h & 3;
    const int base = (b * NKV + hk) * NSPLIT;

    float M = -1e30f;
#pragma unroll
    for (int s = 0; s < NSPLIT; s++) M = fmaxf(M, g_m[(base + s) * 4 + j]);
    float den = 0.f, o = 0.f;
#pragma unroll
    for (int s = 0; s < NSPLIT; s++) {
        const float w = __expf(g_m[(base + s) * 4 + j] - M);
        den += g_l[(base + s) * 4 + j] * w;
        o   += g_op[((size_t)(base + s) * 4 + j) * HD + d] * w;
    }
    g_attn[b * DIM + h * HD + d] = o / den;
}

// ---------------------------------------------------------------------------
// Kernel 5: output GEMV, same block-shared scheme.  1024 blocks, 3/SM.
// ---------------------------------------------------------------------------
__global__ void __launch_bounds__(256, 3) k_gemv_out(
    const float* __restrict__ wo)
{
    const int warp = threadIdx.x >> 5;
    const int lane = threadIdx.x & 31;
    const int cs   = blockIdx.x & 1;
    const int bh   = (blockIdx.x >> 1) & 1;
    const int rb   = blockIdx.x >> 2;          // 0..255
    const int r0   = rb * 16 + warp * 2;
    const int b0   = bh * 8;
    const int c0   = cs * 2048;

    const float* w0p = wo + (size_t)(r0 + 0) * DIM + c0;
    const float* w1p = wo + (size_t)(r0 + 1) * DIM + c0;
    const float* xp  = g_attn + (size_t)b0 * DIM + c0;

    unsigned long long acc[2][8];
#pragma unroll
    for (int r = 0; r < 2; r++)
#pragma unroll
        for (int b = 0; b < 8; b++) acc[r][b] = 0ull;

    const int off = lane * 4;
    for (int c = 0; c < 2048; c += 128) {
        const ulonglong2 w0 = *reinterpret_cast<const ulonglong2*>(w0p + c + off);
        const ulonglong2 w1 = *reinterpret_cast<const ulonglong2*>(w1p + c + off);
#pragma unroll
        for (int b = 0; b < 8; b++) {
            const ulonglong2 xv =
                *reinterpret_cast<const ulonglong2*>(xp + (size_t)b * DIM + c + off);
            acc[0][b] = ffma2(w0.x, xv.x, acc[0][b]);
            acc[0][b] = ffma2(w0.y, xv.y, acc[0][b]);
            acc[1][b] = ffma2(w1.x, xv.x, acc[1][b]);
            acc[1][b] = ffma2(w1.y, xv.y, acc[1][b]);
        }
    }

#pragma unroll
    for (int r = 0; r < 2; r++) {
        float res = 0.f;
#pragma unroll
        for (int b = 0; b < 8; b++) {
            float v = ull_lo(acc[r][b]) + ull_hi(acc[r][b]);
            v += __shfl_xor_sync(0xffffffffu, v, 16);
            v += __shfl_xor_sync(0xffffffffu, v, 8);
            v += __shfl_xor_sync(0xffffffffu, v, 4);
            v += __shfl_xor_sync(0xffffffffu, v, 2);
            v += __shfl_xor_sync(0xffffffffu, v, 1);
            if (lane == b) res = v;
        }
        if (lane < 8)
            g_po[((size_t)cs * DIM + r0 + r) * BSZ + b0 + lane] = res;
    }
}

// ---------------------------------------------------------------------------
// Kernel 6: combine output col-split partials -> d_out.
// ---------------------------------------------------------------------------
__global__ void k_ocomb(float* __restrict__ out)
{
    const int t = blockIdx.x * blockDim.x + threadIdx.x;
    const int b = t >> 12, row = t & 4095;
    out[(size_t)b * DIM + row] =
        g_po[(size_t)row * BSZ + b] + g_po[((size_t)DIM + row) * BSZ + b];
}

// ---------------------------------------------------------------------------
extern "C" void kernel_launch(void* const* d_in, const int* in_sizes, int n_in,
                              void* d_out, int out_size)
{
    const float* x  = (const float*)d_in[0];
    const float* wq = (const float*)d_in[1];
    const float* wk = (const float*)d_in[2];
    const float* wv = (const float*)d_in[3];
    const float* wo = (const float*)d_in[4];
    const float* ck = (const float*)d_in[5];
    const float* cv = (const float*)d_in[6];
    const float* fc = (const float*)d_in[7];
    const float* fs = (const float*)d_in[8];
    const int*   sp = (const int*)d_in[9];
    float* out = (float*)d_out;

    k_gemv_qkv<<<1536, 256>>>(x, wq, wk, wv);
    k_fuse<<<224, 256>>>(fc, fs);
    dim3 ag(NSPLIT, NKV, BSZ);
    k_attn<<<ag, 256>>>(ck, cv, sp);
    k_combine<<<BSZ * NH, HD>>>();
    k_gemv_out<<<1024, 256>>>(wo);
    k_ocomb<<<256, 256>>>(out);
}